// round 5
// baseline (speedup 1.0000x reference)
#include <cuda_runtime.h>
#include <stdint.h>

#define VOCAB 512
#define WCHARS 24
#define WPB 8          // warps per block

// One warp per (b,s) row, NO shared memory:
//   1) zero the 2KB output row with 16x STG.128 (issues while LDG is in flight)
//   2) fence, then RED.ADD.F32 (fire-and-forget global atomics) for the <=24
//      weighted chars.
// Tail output (lengths) fused into block 0. int64 inputs arrive as int32
// (jax x64 disabled).
__global__ void __launch_bounds__(WPB * 32)
fofe_kernel(const int* __restrict__ sents,
            const int* __restrict__ lengths,
            const float* __restrict__ alpha_p,
            float* __restrict__ out,
            int nrows,
            long long main_elems,
            int extra,
            int nlen)
{
    const int warp = threadIdx.x >> 5;
    const int lane = threadIdx.x & 31;
    const int row  = blockIdx.x * WPB + warp;

    // fused tail: (out, lengths) second output appended to d_out
    if (blockIdx.x == 0 && (int)threadIdx.x < extra) {
        int i = threadIdx.x;
        out[main_elems + i] = (i < nlen) ? (float)lengths[i] : 0.0f;
    }
    if (row >= nrows) return;

    // kick off the input load first so its latency overlaps the zero-fill
    int c = 0;
    if (lane < WCHARS)
        c = sents[(long long)row * WCHARS + lane];
    const float a = __ldg(alpha_p);

    // zero the row: 4 x STG.128 per lane, coalesced, evict-first
    float* orow = out + (long long)row * VOCAB;
    float4* o4  = reinterpret_cast<float4*>(orow);
    const float4 z = make_float4(0.f, 0.f, 0.f, 0.f);
    #pragma unroll
    for (int j = 0; j < 4; ++j)
        __stcs(&o4[j * 32 + lane], z);

    const bool valid = (lane < WCHARS) && (c > 0) && (c < VOCAB);
    const unsigned nz = __ballot_sync(0xffffffffu, valid);

    // order this lane's zero-stores before any lane's atomics
    __threadfence();
    __syncwarp();

    if (valid) {
        // # of nonzero chars strictly after this lane
        const int suffix = __popc(nz & (0xfffffffeu << lane));
        const float w = (suffix == 0) ? 1.0f
                                      : exp2f(log2f(a) * (float)suffix);
        atomicAdd(&orow[c], w);        // RED.ADD.F32, no return
    }
}

extern "C" void kernel_launch(void* const* d_in, const int* in_sizes, int n_in,
                              void* d_out, int out_size)
{
    const int*   sents   = (const int*)d_in[0];
    const int*   lengths = (const int*)d_in[1];
    const float* alpha   = (const float*)d_in[2];
    float*       out     = (float*)d_out;

    const int nrows = in_sizes[0] / WCHARS;             // B*S = 32768
    const long long main_elems = (long long)nrows * VOCAB;
    const int nlen = in_sizes[1];

    long long extra_ll = (long long)out_size - main_elems;
    if (extra_ll < 0) extra_ll = 0;
    if (extra_ll > WPB * 32) extra_ll = WPB * 32;

    const int blocks = (nrows + WPB - 1) / WPB;
    fofe_kernel<<<blocks, WPB * 32>>>(sents, lengths, alpha, out,
                                      nrows, main_elems, (int)extra_ll, nlen);
}

// round 6
// speedup vs baseline: 1.2553x; 1.2553x over previous
#include <cuda_runtime.h>
#include <stdint.h>

#define VOCAB 512
#define WCHARS 24
#define WPB 8          // warps per block == rows per block

// One warp per (b,s) row. Per-warp 512-bin histogram in smem laid out exactly
// like the 8 contiguous output rows of this block; a single elected thread
// then bulk-copies all 16KB smem -> global via TMA (cp.async.bulk), removing
// all per-thread STG traffic. Tail output (lengths) fused into block 0.
// int64 inputs arrive as int32 (jax x64 disabled).
__global__ void __launch_bounds__(WPB * 32)
fofe_kernel(const int* __restrict__ sents,
            const int* __restrict__ lengths,
            const float* __restrict__ alpha_p,
            float* __restrict__ out,
            int nrows,
            long long main_elems,
            int extra,
            int nlen)
{
    __shared__ __align__(128) float hist[WPB][VOCAB];   // 16 KB

    const int warp = threadIdx.x >> 5;
    const int lane = threadIdx.x & 31;
    const int row0 = blockIdx.x * WPB;
    const int row  = row0 + warp;
    const int rows_here = min(WPB, nrows - row0);       // partial last block

    // fused tail: (out, lengths) second output appended to d_out
    if (blockIdx.x == 0 && (int)threadIdx.x < extra) {
        int i = threadIdx.x;
        out[main_elems + i] = (i < nlen) ? (float)lengths[i] : 0.0f;
    }

    if (warp < rows_here) {
        float* h = hist[warp];

        // input load first; zero-fill overlaps its latency
        int c = 0;
        if (lane < WCHARS)
            c = sents[(long long)row * WCHARS + lane];
        const float a = __ldg(alpha_p);

        // zero the 2KB row histogram: 4 x STS.128 per lane
        float4* h4 = reinterpret_cast<float4*>(h);
        const float4 z = make_float4(0.f, 0.f, 0.f, 0.f);
        #pragma unroll
        for (int j = 0; j < 4; ++j)
            h4[j * 32 + lane] = z;

        const bool valid = (lane < WCHARS) && (c > 0) && (c < VOCAB);
        const unsigned nz = __ballot_sync(0xffffffffu, valid);
        __syncwarp();                       // zeros visible before atomics

        if (valid) {
            const int suffix = __popc(nz & (0xfffffffeu << lane));
            const float w = (suffix == 0) ? 1.0f
                                          : exp2f(log2f(a) * (float)suffix);
            atomicAdd(&h[c], w);            // shared atomic, <=24 per row
        }
    }

    __syncthreads();                        // all histograms complete

    // Elected thread bulk-copies rows_here*2KB smem -> out via TMA.
    if (threadIdx.x == 0) {
        asm volatile("fence.proxy.async.shared::cta;" ::: "memory");
        unsigned saddr = (unsigned)__cvta_generic_to_shared(&hist[0][0]);
        float*   gdst  = out + (long long)row0 * VOCAB;
        unsigned bytes = (unsigned)rows_here * VOCAB * sizeof(float);
        asm volatile(
            "cp.async.bulk.global.shared::cta.bulk_group [%0], [%1], %2;"
            :: "l"(gdst), "r"(saddr), "r"(bytes) : "memory");
        asm volatile("cp.async.bulk.commit_group;" ::: "memory");
        // keep the block (and its smem) alive until the TMA read completes
        asm volatile("cp.async.bulk.wait_group 0;" ::: "memory");
    }
}

extern "C" void kernel_launch(void* const* d_in, const int* in_sizes, int n_in,
                              void* d_out, int out_size)
{
    const int*   sents   = (const int*)d_in[0];
    const int*   lengths = (const int*)d_in[1];
    const float* alpha   = (const float*)d_in[2];
    float*       out     = (float*)d_out;

    const int nrows = in_sizes[0] / WCHARS;             // B*S = 32768
    const long long main_elems = (long long)nrows * VOCAB;
    const int nlen = in_sizes[1];

    long long extra_ll = (long long)out_size - main_elems;
    if (extra_ll < 0) extra_ll = 0;
    if (extra_ll > WPB * 32) extra_ll = WPB * 32;

    const int blocks = (nrows + WPB - 1) / WPB;
    fofe_kernel<<<blocks, WPB * 32>>>(sents, lengths, alpha, out,
                                      nrows, main_elems, (int)extra_ll, nlen);
}